// round 7
// baseline (speedup 1.0000x reference)
#include <cuda_runtime.h>
#include <math.h>

// Problem constants: B=8, C=512, H=W=32 (HW=1024), 8 heads x 64 dim, 32 groups.
// Activations are kept in [channel][b*1024+hw] layout (NCOL = 8*1024 = 8192)
// so both 1x1 convs become single large GEMMs.

#define NCOL 8192

// Scratch (allocation-free rule: __device__ globals)
__device__ float g_xnt [512  * NCOL];   // normalized input, [c][b*HW+hw]
__device__ float g_qkv [1536 * NCOL];   // qkv, row o = head*192 + {q:0..63, k:64..127, v:128..191}
__device__ float g_attn[512  * NCOL];   // attention output, row c = head*64 + d

// ---------------------------------------------------------------------------
// GroupNorm: one block per (b, group). group = 16 ch x 1024 px = 16384 floats.
// ---------------------------------------------------------------------------
__global__ __launch_bounds__(256) void gn_kernel(const float* __restrict__ x,
                                                 const float* __restrict__ gamma,
                                                 const float* __restrict__ beta)
{
    int b = blockIdx.x >> 5;
    int g = blockIdx.x & 31;
    const float4* xg = (const float4*)(x + ((b * 512 + g * 16) << 10));
    int tid = threadIdx.x;

    float4 v[16];
    float s = 0.f, ss = 0.f;
#pragma unroll
    for (int i = 0; i < 16; i++) {
        float4 t = xg[i * 256 + tid];
        v[i] = t;
        s  += t.x + t.y + t.z + t.w;
        ss += t.x * t.x + t.y * t.y + t.z * t.z + t.w * t.w;
    }
#pragma unroll
    for (int off = 16; off; off >>= 1) {
        s  += __shfl_xor_sync(0xffffffffu, s,  off);
        ss += __shfl_xor_sync(0xffffffffu, ss, off);
    }
    __shared__ float red[8][2];
    __shared__ float stats[2];
    int warp = tid >> 5, lane = tid & 31;
    if (lane == 0) { red[warp][0] = s; red[warp][1] = ss; }
    __syncthreads();
    if (tid == 0) {
        float S = 0.f, SS = 0.f;
#pragma unroll
        for (int w = 0; w < 8; w++) { S += red[w][0]; SS += red[w][1]; }
        float mean = S * (1.f / 16384.f);
        float var  = SS * (1.f / 16384.f) - mean * mean;
        stats[0] = mean;
        stats[1] = rsqrtf(var + 1e-5f);
    }
    __syncthreads();
    float mean = stats[0], rstd = stats[1];

    float4* xnt4 = (float4*)g_xnt;
#pragma unroll
    for (int i = 0; i < 16; i++) {
        int idx4 = i * 256 + tid;
        int cl   = idx4 >> 8;
        int hw4  = idx4 & 255;
        int c    = g * 16 + cl;
        float ga = gamma[c] * rstd;
        float bb = beta[c] - mean * ga;
        float4 t = v[i], o;
        o.x = t.x * ga + bb; o.y = t.y * ga + bb;
        o.z = t.z * ga + bb; o.w = t.w * ga + bb;
        xnt4[c * 2048 + b * 256 + hw4] = o;
    }
}

// ---------------------------------------------------------------------------
// SGEMM: C = A[M,K] @ B[K,N] (+bias per row), 128x128 tile, BK=8, prefetch.
// MODE 0: C[r*N+n] = acc + bias[r]           (qkv)
// MODE 1: out[(b*512+r)*1024+hw] = acc + bias[r] + resid[...]  (proj+residual)
// ---------------------------------------------------------------------------
template <int MODE>
__global__ __launch_bounds__(256) void sgemm_kernel(
        const float* __restrict__ A, const float* __restrict__ Bm,
        const float* __restrict__ bias, const float* __restrict__ resid,
        float* __restrict__ C, int M, int N, int K)
{
    __shared__ float As[8][128];
    __shared__ float Bs[8][128];

    int tid = threadIdx.x;
    int m0 = blockIdx.y << 7, n0 = blockIdx.x << 7;
    int tx = tid & 15, ty = tid >> 4;

    int arow = tid >> 1,      acol = (tid & 1)  << 2;
    int brow = tid >> 5,      bcol = (tid & 31) << 2;
    const float* Aptr = A  + (m0 + arow) * K + acol;
    const float* Bptr = Bm + brow * N + n0 + bcol;

    float acc[8][8];
#pragma unroll
    for (int i = 0; i < 8; i++)
#pragma unroll
        for (int j = 0; j < 8; j++) acc[i][j] = 0.f;

    float4 a4 = *(const float4*)(Aptr);
    float4 b4 = *(const float4*)(Bptr);

    for (int k0 = 0; k0 < K; k0 += 8) {
        As[acol + 0][arow] = a4.x; As[acol + 1][arow] = a4.y;
        As[acol + 2][arow] = a4.z; As[acol + 3][arow] = a4.w;
        *(float4*)&Bs[brow][bcol] = b4;
        __syncthreads();

        if (k0 + 8 < K) {
            a4 = *(const float4*)(Aptr + k0 + 8);
            b4 = *(const float4*)(Bptr + (k0 + 8) * N);
        }

#pragma unroll
        for (int k = 0; k < 8; k++) {
            float ar[8], br[8];
            *(float4*)&ar[0] = *(const float4*)&As[k][ty * 4];
            *(float4*)&ar[4] = *(const float4*)&As[k][64 + ty * 4];
            *(float4*)&br[0] = *(const float4*)&Bs[k][tx * 4];
            *(float4*)&br[4] = *(const float4*)&Bs[k][64 + tx * 4];
#pragma unroll
            for (int i = 0; i < 8; i++)
#pragma unroll
                for (int j = 0; j < 8; j++)
                    acc[i][j] = fmaf(ar[i], br[j], acc[i][j]);
        }
        __syncthreads();
    }

#pragma unroll
    for (int hi = 0; hi < 2; hi++)
#pragma unroll
    for (int ii = 0; ii < 4; ii++) {
        int r = m0 + hi * 64 + ty * 4 + ii;
        float bv = bias[r];
#pragma unroll
        for (int hj = 0; hj < 2; hj++) {
            int cb = n0 + hj * 64 + tx * 4;
            float4 o;
            o.x = acc[hi * 4 + ii][hj * 4 + 0] + bv;
            o.y = acc[hi * 4 + ii][hj * 4 + 1] + bv;
            o.z = acc[hi * 4 + ii][hj * 4 + 2] + bv;
            o.w = acc[hi * 4 + ii][hj * 4 + 3] + bv;
            if (MODE == 0) {
                *(float4*)&C[r * N + cb] = o;
            } else {
                int bidx = cb >> 10;
                int hw   = cb & 1023;
                int oidx = ((bidx << 9) + r) * 1024 + hw;
                float4 rv = *(const float4*)&resid[oidx];
                o.x += rv.x; o.y += rv.y; o.z += rv.z; o.w += rv.w;
                *(float4*)&C[oidx] = o;
            }
        }
    }
}

// ---------------------------------------------------------------------------
// Flash attention v2, fp32. Grid: (16 q-tiles, 64 b*head). 256 threads.
// BQ=64 queries/block, BKV=64 keys/tile, d=64.
// Dynamic smem (50944 B):
//   Qs[64][64]  (Q^T: [d][q])
//   Ks[64][64]  ([d][j], aliased as P[64][64] after S computed)
//   Vt[64][68]  (transposed [j][d]; pad 68 keeps rows 16B-aligned for float4)
//   m_s/l_s/alpha_s[64]
// Next K/V tile prefetched into registers during compute.
// ---------------------------------------------------------------------------
__global__ __launch_bounds__(256) void attn_kernel()
{
    extern __shared__ float sm[];
    float (*Qs)[64] = (float(*)[64])sm;              // 4096 floats
    float (*Ks)[64] = (float(*)[64])(sm + 4096);     // 4096 floats
    float (*Vt)[68] = (float(*)[68])(sm + 8192);     // 4352 floats
    float* m_s     = sm + 8192 + 4352;               // 64
    float* l_s     = m_s + 64;                       // 64
    float* alpha_s = l_s + 64;                       // 64
    float* Ss      = &Ks[0][0];                      // P alias

    int tid  = threadIdx.x;
    int bh   = blockIdx.y;
    int b    = bh >> 3, head = bh & 7;
    int q0   = blockIdx.x << 6;

    const float* qp = g_qkv + (head * 192      ) * NCOL + b * 1024 + q0;
    const float* kp = g_qkv + (head * 192 +  64) * NCOL + b * 1024;
    const float* vp = g_qkv + (head * 192 + 128) * NCOL + b * 1024;

    // Q tile: 64x64 floats = 1024 float4, 4 per thread
    {
        int d  = tid >> 4;          // base row for rep stride 16
        int i4 = tid & 15;
#pragma unroll
        for (int rep = 0; rep < 4; rep++)
            *(float4*)&Qs[rep * 16 + d][i4 << 2] =
                *(const float4*)(qp + (rep * 16 + d) * NCOL + (i4 << 2));
    }
    if (tid < 64) { m_s[tid] = -1e30f; l_s[tid] = 0.f; }

    int tx = tid & 15, ty = tid >> 4;   // rows q = ty*4.., cols = tx*4..
    float acc[4][4];
#pragma unroll
    for (int a = 0; a < 4; a++)
#pragma unroll
        for (int c = 0; c < 4; c++) acc[a][c] = 0.f;

    // prefetch registers for K/V tiles (4 float4 each)
    int pd  = tid >> 4;         // row within 16-row slab
    int pj4 = tid & 15;         // float4 col
    float4 kr[4], vr[4];
#pragma unroll
    for (int rep = 0; rep < 4; rep++) {
        kr[rep] = *(const float4*)(kp + (rep * 16 + pd) * NCOL + (pj4 << 2));
        vr[rep] = *(const float4*)(vp + (rep * 16 + pd) * NCOL + (pj4 << 2));
    }
    __syncthreads();   // Q + stats ready (also covers kt=0 smem store safety)

    for (int kt = 0; kt < 16; kt++) {
        // store prefetched tile to smem
#pragma unroll
        for (int rep = 0; rep < 4; rep++) {
            int d = rep * 16 + pd;
            *(float4*)&Ks[d][pj4 << 2] = kr[rep];
            float4 vv = vr[rep];
            Vt[(pj4 << 2) + 0][d] = vv.x;
            Vt[(pj4 << 2) + 1][d] = vv.y;
            Vt[(pj4 << 2) + 2][d] = vv.z;
            Vt[(pj4 << 2) + 3][d] = vv.w;
        }
        __syncthreads();   // S1: tile visible

        if (kt < 15) {     // prefetch next tile during compute
            int j0n = (kt + 1) << 6;
#pragma unroll
            for (int rep = 0; rep < 4; rep++) {
                kr[rep] = *(const float4*)(kp + (rep * 16 + pd) * NCOL + j0n + (pj4 << 2));
                vr[rep] = *(const float4*)(vp + (rep * 16 + pd) * NCOL + j0n + (pj4 << 2));
            }
        }

        // S = Q^T K  (4x4 per thread)
        float s[4][4];
#pragma unroll
        for (int a = 0; a < 4; a++)
#pragma unroll
            for (int c = 0; c < 4; c++) s[a][c] = 0.f;
#pragma unroll 16
        for (int d = 0; d < 64; d++) {
            float4 qa = *(const float4*)&Qs[d][ty << 2];
            float4 kb = *(const float4*)&Ks[d][tx << 2];
            s[0][0] = fmaf(qa.x, kb.x, s[0][0]); s[0][1] = fmaf(qa.x, kb.y, s[0][1]);
            s[0][2] = fmaf(qa.x, kb.z, s[0][2]); s[0][3] = fmaf(qa.x, kb.w, s[0][3]);
            s[1][0] = fmaf(qa.y, kb.x, s[1][0]); s[1][1] = fmaf(qa.y, kb.y, s[1][1]);
            s[1][2] = fmaf(qa.y, kb.z, s[1][2]); s[1][3] = fmaf(qa.y, kb.w, s[1][3]);
            s[2][0] = fmaf(qa.z, kb.x, s[2][0]); s[2][1] = fmaf(qa.z, kb.y, s[2][1]);
            s[2][2] = fmaf(qa.z, kb.z, s[2][2]); s[2][3] = fmaf(qa.z, kb.w, s[2][3]);
            s[3][0] = fmaf(qa.w, kb.x, s[3][0]); s[3][1] = fmaf(qa.w, kb.y, s[3][1]);
            s[3][2] = fmaf(qa.w, kb.z, s[3][2]); s[3][3] = fmaf(qa.w, kb.w, s[3][3]);
        }
        __syncthreads();   // S2: done reading Ks -> safe to overwrite as P

        // store scaled scores into P tile
#pragma unroll
        for (int ii = 0; ii < 4; ii++) {
            float4 p;
            p.x = s[ii][0] * 0.125f; p.y = s[ii][1] * 0.125f;
            p.z = s[ii][2] * 0.125f; p.w = s[ii][3] * 0.125f;
            *(float4*)&Ss[((ty << 2) + ii) * 64 + (tx << 2)] = p;
        }
        __syncthreads();   // S3: P complete

        // online softmax: 4 threads per row, 16 elems each (within one warp)
        {
            int r = tid >> 2, part = tid & 3;
            float* row = &Ss[r * 64 + part * 16];
            float mx = -1e30f;
#pragma unroll
            for (int t = 0; t < 16; t++) mx = fmaxf(mx, row[t]);
            mx = fmaxf(mx, __shfl_xor_sync(0xffffffffu, mx, 1));
            mx = fmaxf(mx, __shfl_xor_sync(0xffffffffu, mx, 2));
            float m_old = m_s[r];
            float m_new = fmaxf(m_old, mx);
            float sum = 0.f;
#pragma unroll
            for (int t = 0; t < 16; t++) {
                float p = __expf(row[t] - m_new);
                row[t] = p;
                sum += p;
            }
            sum += __shfl_xor_sync(0xffffffffu, sum, 1);
            sum += __shfl_xor_sync(0xffffffffu, sum, 2);
            if (part == 0) {
                float al = __expf(m_old - m_new);
                m_s[r] = m_new;
                l_s[r] = l_s[r] * al + sum;
                alpha_s[r] = al;
            }
        }
        __syncthreads();   // S4: softmax + alpha done

        // O = O*alpha + P @ V^T
#pragma unroll
        for (int ii = 0; ii < 4; ii++) {
            float al = alpha_s[(ty << 2) + ii];
            acc[ii][0] *= al; acc[ii][1] *= al; acc[ii][2] *= al; acc[ii][3] *= al;
        }
#pragma unroll 8
        for (int j = 0; j < 64; j++) {
            float4 v4 = *(const float4*)&Vt[j][tx << 2];
#pragma unroll
            for (int ii = 0; ii < 4; ii++) {
                float p = Ss[((ty << 2) + ii) * 64 + j];
                acc[ii][0] = fmaf(p, v4.x, acc[ii][0]);
                acc[ii][1] = fmaf(p, v4.y, acc[ii][1]);
                acc[ii][2] = fmaf(p, v4.z, acc[ii][2]);
                acc[ii][3] = fmaf(p, v4.w, acc[ii][3]);
            }
        }
        __syncthreads();   // S5: before next tile overwrites Ks/Vt
    }

    // epilogue: normalize and write [c = head*64+d][b*1024 + q]
    float* outp = g_attn + (head * 64) * NCOL + b * 1024 + q0;
#pragma unroll
    for (int ii = 0; ii < 4; ii++) {
        float inv = 1.f / l_s[(ty << 2) + ii];
#pragma unroll
        for (int dd = 0; dd < 4; dd++)
            outp[((tx << 2) + dd) * NCOL + (ty << 2) + ii] = acc[ii][dd] * inv;
    }
}

#define ATTN_SMEM_BYTES 50944

// ---------------------------------------------------------------------------
extern "C" void kernel_launch(void* const* d_in, const int* in_sizes, int n_in,
                              void* d_out, int out_size)
{
    const float* x    = (const float*)d_in[0];
    const float* gnw  = (const float*)d_in[1];
    const float* gnb  = (const float*)d_in[2];
    const float* qkvw = (const float*)d_in[3];
    const float* qkvb = (const float*)d_in[4];
    const float* outw = (const float*)d_in[5];
    const float* outb = (const float*)d_in[6];
    float* out = (float*)d_out;

    float *xnt, *qkv, *attn;
    cudaGetSymbolAddress((void**)&xnt,  g_xnt);
    cudaGetSymbolAddress((void**)&qkv,  g_qkv);
    cudaGetSymbolAddress((void**)&attn, g_attn);

    cudaFuncSetAttribute(attn_kernel,
                         cudaFuncAttributeMaxDynamicSharedMemorySize,
                         ATTN_SMEM_BYTES);

    // 1. GroupNorm (writes transposed activations)
    gn_kernel<<<256, 256>>>(x, gnw, gnb);
    // 2. QKV projection: [1536,512] @ [512,8192]
    sgemm_kernel<0><<<dim3(64, 12), 256>>>(qkvw, xnt, qkvb, nullptr, qkv, 1536, NCOL, 512);
    // 3. Flash attention per (b, head)
    attn_kernel<<<dim3(16, 64), 256, ATTN_SMEM_BYTES>>>();
    // 4. Output projection + bias + residual: [512,512] @ [512,8192] -> d_out
    sgemm_kernel<1><<<dim3(64, 4), 256>>>(outw, attn, outb, x, out, 512, NCOL, 512);
}

// round 9
// speedup vs baseline: 2.3442x; 2.3442x over previous
#include <cuda_runtime.h>
#include <cuda_bf16.h>
#include <math.h>

// B=8, C=512, H=W=32 (HW=1024), 8 heads x 64 dim, 32 groups. NCOL = 8*1024.
#define NCOL 8192

// Scratch (__device__ globals; no allocation allowed)
__device__ __nv_bfloat16 g_xnt [NCOL * 512];    // normalized input, PIXEL-major [n][c]
__device__ float         g_qkv [1536 * NCOL];   // qkv fp32, row o = head*192 + {q,k,v}
__device__ __nv_bfloat16 g_attn[NCOL * 512];    // attention out, PIXEL-major [n][c]
__device__ __nv_bfloat16 g_wqkv[1536 * 512];    // bf16 weights
__device__ __nv_bfloat16 g_wout[512 * 512];

// ---------------------------------------------------------------------------
// Weight fp32 -> bf16 conversion. 1024 blocks x 256 thr, one float4 each.
// ---------------------------------------------------------------------------
__global__ __launch_bounds__(256) void cvt_kernel(const float* __restrict__ w1,
                                                  const float* __restrict__ w2)
{
    int i = blockIdx.x * 256 + threadIdx.x;
    const float4* src;
    __nv_bfloat16* dst;
    int idx = i;
    if (idx < 196608) { src = (const float4*)w1; dst = g_wqkv; }          // 1536*512/4
    else { idx -= 196608; src = (const float4*)w2; dst = g_wout; }        // 512*512/4
    float4 f = src[idx];
    __nv_bfloat162 h0 = __floats2bfloat162_rn(f.x, f.y);
    __nv_bfloat162 h1 = __floats2bfloat162_rn(f.z, f.w);
    uint2 u = make_uint2(*(unsigned*)&h0, *(unsigned*)&h1);
    *(uint2*)(dst + idx * 4) = u;
}

// ---------------------------------------------------------------------------
// GroupNorm: block per (b, group) = 16 ch x 1024 px. Writes bf16 [n][c].
// ---------------------------------------------------------------------------
__global__ __launch_bounds__(256) void gn_kernel(const float* __restrict__ x,
                                                 const float* __restrict__ gamma,
                                                 const float* __restrict__ beta)
{
    int b = blockIdx.x >> 5;
    int g = blockIdx.x & 31;
    const float4* xg = (const float4*)(x + ((b * 512 + g * 16) << 10));
    int tid = threadIdx.x;

    float4 v[16];
    float* vf = (float*)v;
    float s = 0.f, ss = 0.f;
#pragma unroll
    for (int i = 0; i < 16; i++) {
        float4 t = xg[i * 256 + tid];
        v[i] = t;
        s  += t.x + t.y + t.z + t.w;
        ss += t.x * t.x + t.y * t.y + t.z * t.z + t.w * t.w;
    }
#pragma unroll
    for (int off = 16; off; off >>= 1) {
        s  += __shfl_xor_sync(0xffffffffu, s,  off);
        ss += __shfl_xor_sync(0xffffffffu, ss, off);
    }
    __shared__ float red[8][2];
    __shared__ float stats[2];
    int warp = tid >> 5, lane = tid & 31;
    if (lane == 0) { red[warp][0] = s; red[warp][1] = ss; }
    __syncthreads();
    if (tid == 0) {
        float S = 0.f, SS = 0.f;
#pragma unroll
        for (int w = 0; w < 8; w++) { S += red[w][0]; SS += red[w][1]; }
        float mean = S * (1.f / 16384.f);
        float var  = SS * (1.f / 16384.f) - mean * mean;
        stats[0] = mean;
        stats[1] = rsqrtf(var + 1e-5f);
    }
    __syncthreads();
    float mean = stats[0], rstd = stats[1];

    // normalize in place
#pragma unroll
    for (int i = 0; i < 16; i++) {
        int c = g * 16 + i;
        float ga = gamma[c] * rstd;
        float bb = beta[c] - mean * ga;
        v[i].x = v[i].x * ga + bb; v[i].y = v[i].y * ga + bb;
        v[i].z = v[i].z * ga + bb; v[i].w = v[i].w * ga + bb;
    }
    // write 4 pixels x 16 channels, bf16, pixel-major
#pragma unroll
    for (int j = 0; j < 4; j++) {
        unsigned u[8];
#pragma unroll
        for (int k2 = 0; k2 < 8; k2++) {
            __nv_bfloat162 h = __floats2bfloat162_rn(vf[(2 * k2) * 4 + j],
                                                     vf[(2 * k2 + 1) * 4 + j]);
            u[k2] = *(unsigned*)&h;
        }
        size_t off = (size_t)(b * 1024 + tid * 4 + j) * 512 + g * 16;
        *(uint4*)(g_xnt + off)     = make_uint4(u[0], u[1], u[2], u[3]);
        *(uint4*)(g_xnt + off + 8) = make_uint4(u[4], u[5], u[6], u[7]);
    }
}

// ---------------------------------------------------------------------------
// bf16 HMMA helpers (mma.sync m16n8k16, f32 accum)
// ---------------------------------------------------------------------------
__device__ __forceinline__ void ldsm_x4(unsigned& r0, unsigned& r1,
                                        unsigned& r2, unsigned& r3, unsigned addr) {
    asm volatile("ldmatrix.sync.aligned.m8n8.x4.shared.b16 {%0,%1,%2,%3}, [%4];"
                 : "=r"(r0), "=r"(r1), "=r"(r2), "=r"(r3) : "r"(addr));
}
__device__ __forceinline__ void ldsm_x2(unsigned& r0, unsigned& r1, unsigned addr) {
    asm volatile("ldmatrix.sync.aligned.m8n8.x2.shared.b16 {%0,%1}, [%2];"
                 : "=r"(r0), "=r"(r1) : "r"(addr));
}
__device__ __forceinline__ void mma16816(float* c, const unsigned* a, const unsigned* b) {
    asm volatile("mma.sync.aligned.m16n8k16.row.col.f32.bf16.bf16.f32 "
                 "{%0,%1,%2,%3}, {%4,%5,%6,%7}, {%8,%9}, {%0,%1,%2,%3};"
                 : "+f"(c[0]), "+f"(c[1]), "+f"(c[2]), "+f"(c[3])
                 : "r"(a[0]), "r"(a[1]), "r"(a[2]), "r"(a[3]), "r"(b[0]), "r"(b[1]));
}

// ---------------------------------------------------------------------------
// HGEMM: C[M,8192] = A[M,512] @ Bt[8192,512]^T, bf16 in / fp32 out.
// CTA tile 128x128, K-step 32, 8 warps (2 M x 4 N), warp tile 64x32.
// Both smem tiles are 128 rows x 32 bf16 (64B rows), XOR-swizzled
// (chunk ^= (row>>1)&3) so ldmatrix phases are conflict-free.
// MODE 0: C[r*8192+n] = acc + bias[r]                      (qkv, fp32 out)
// MODE 1: out[(b*512+r)*1024+hw] = acc + bias[r] + resid   (proj+residual)
// ---------------------------------------------------------------------------
template <int MODE>
__global__ __launch_bounds__(256) void hgemm_kernel(
        const __nv_bfloat16* __restrict__ A,
        const __nv_bfloat16* __restrict__ Bt,
        const float* __restrict__ bias, const float* __restrict__ resid,
        float* __restrict__ C)
{
    constexpr int K = 512;
    __shared__ __align__(16) __nv_bfloat16 smA[128 * 32];
    __shared__ __align__(16) __nv_bfloat16 smB[128 * 32];

    int tid = threadIdx.x, lane = tid & 31, w = tid >> 5;
    int m0 = blockIdx.y << 7, n0 = blockIdx.x << 7;
    int m0w = (w & 1) << 6, n0w = (w >> 1) << 5;

    // gmem->smem staging: each thread 2 x 16B granules of A and of B
    int ldr  = tid >> 1;              // row 0..127
    int ldg0 = (tid & 1) << 1;        // granule 0 or 2
    const uint4* Ag = (const uint4*)(A  + (m0 + ldr) * K);
    const uint4* Bg = (const uint4*)(Bt + (n0 + ldr) * K);
    int swz = (ldr >> 1) & 3;
    uint4* sA4 = (uint4*)smA;
    uint4* sB4 = (uint4*)smB;
    int s0 = ldr * 4 + (ldg0 ^ swz);
    int s1 = ldr * 4 + ((ldg0 + 1) ^ swz);

    unsigned baseA = (unsigned)__cvta_generic_to_shared(smA);
    unsigned baseB = (unsigned)__cvta_generic_to_shared(smB);

    float acc[4][4][4] = {};
    uint4 pa0 = Ag[ldg0], pa1 = Ag[ldg0 + 1];
    uint4 pb0 = Bg[ldg0], pb1 = Bg[ldg0 + 1];

    for (int k0 = 0; k0 < K; k0 += 32) {
        sA4[s0] = pa0; sA4[s1] = pa1;
        sB4[s0] = pb0; sB4[s1] = pb1;
        __syncthreads();
        if (k0 + 32 < K) {
            int kg = (k0 + 32) >> 3;
            pa0 = Ag[kg + ldg0]; pa1 = Ag[kg + ldg0 + 1];
            pb0 = Bg[kg + ldg0]; pb1 = Bg[kg + ldg0 + 1];
        }
#pragma unroll
        for (int kk = 0; kk < 32; kk += 16) {
            unsigned af[4][4], bf[4][2];
#pragma unroll
            for (int mt = 0; mt < 4; mt++) {
                int r  = m0w + mt * 16 + (lane & 15);
                int ch = (kk >> 3) + (lane >> 4);
                ldsm_x4(af[mt][0], af[mt][1], af[mt][2], af[mt][3],
                        baseA + r * 64 + ((ch ^ ((r >> 1) & 3)) << 4));
            }
#pragma unroll
            for (int nt = 0; nt < 4; nt++) {
                int l  = lane & 15;
                int r  = n0w + nt * 8 + (l & 7);
                int ch = (kk >> 3) + (l >> 3);
                ldsm_x2(bf[nt][0], bf[nt][1],
                        baseB + r * 64 + ((ch ^ ((r >> 1) & 3)) << 4));
            }
#pragma unroll
            for (int mt = 0; mt < 4; mt++)
#pragma unroll
                for (int nt = 0; nt < 4; nt++)
                    mma16816(acc[mt][nt], af[mt], bf[nt]);
        }
        __syncthreads();
    }

    // epilogue
    int gid = lane >> 2, qid = lane & 3;
#pragma unroll
    for (int mt = 0; mt < 4; mt++) {
        int row = m0 + m0w + mt * 16 + gid;
        float bv0 = bias[row], bv1 = bias[row + 8];
#pragma unroll
        for (int nt = 0; nt < 4; nt++) {
            int col = n0 + n0w + nt * 8 + (qid << 1);
            float2 lo = make_float2(acc[mt][nt][0] + bv0, acc[mt][nt][1] + bv0);
            float2 hi = make_float2(acc[mt][nt][2] + bv1, acc[mt][nt][3] + bv1);
            if (MODE == 0) {
                *(float2*)&C[row * 8192 + col]       = lo;
                *(float2*)&C[(row + 8) * 8192 + col] = hi;
            } else {
                int bb = col >> 10, hw = col & 1023;
                int i0 = ((bb << 9) + row) * 1024 + hw;
                int i1 = ((bb << 9) + row + 8) * 1024 + hw;
                float2 r0 = *(const float2*)&resid[i0];
                float2 r1 = *(const float2*)&resid[i1];
                lo.x += r0.x; lo.y += r0.y; hi.x += r1.x; hi.y += r1.y;
                *(float2*)&C[i0] = lo;
                *(float2*)&C[i1] = hi;
            }
        }
    }
}

// ---------------------------------------------------------------------------
// Flash attention v2, fp32 (unchanged math). Grid: (16 q-tiles, 64 b*head),
// 256 threads, BQ=64, BKV=64, d=64. Epilogue writes bf16 [n][c] to g_attn.
// ---------------------------------------------------------------------------
__global__ __launch_bounds__(256) void attn_kernel()
{
    extern __shared__ float sm[];
    float (*Qs)[64] = (float(*)[64])sm;              // 4096 floats
    float (*Ks)[64] = (float(*)[64])(sm + 4096);     // 4096 floats
    float (*Vt)[68] = (float(*)[68])(sm + 8192);     // 4352 floats
    float* m_s     = sm + 8192 + 4352;
    float* l_s     = m_s + 64;
    float* alpha_s = l_s + 64;
    float* Ss      = &Ks[0][0];                      // P alias

    int tid  = threadIdx.x;
    int bh   = blockIdx.y;
    int b    = bh >> 3, head = bh & 7;
    int q0   = blockIdx.x << 6;

    const float* qp = g_qkv + (head * 192      ) * NCOL + b * 1024 + q0;
    const float* kp = g_qkv + (head * 192 +  64) * NCOL + b * 1024;
    const float* vp = g_qkv + (head * 192 + 128) * NCOL + b * 1024;

    {
        int d  = tid >> 4;
        int i4 = tid & 15;
#pragma unroll
        for (int rep = 0; rep < 4; rep++)
            *(float4*)&Qs[rep * 16 + d][i4 << 2] =
                *(const float4*)(qp + (rep * 16 + d) * NCOL + (i4 << 2));
    }
    if (tid < 64) { m_s[tid] = -1e30f; l_s[tid] = 0.f; }

    int tx = tid & 15, ty = tid >> 4;
    float acc[4][4];
#pragma unroll
    for (int a = 0; a < 4; a++)
#pragma unroll
        for (int c = 0; c < 4; c++) acc[a][c] = 0.f;

    int pd  = tid >> 4;
    int pj4 = tid & 15;
    float4 kr[4], vr[4];
#pragma unroll
    for (int rep = 0; rep < 4; rep++) {
        kr[rep] = *(const float4*)(kp + (rep * 16 + pd) * NCOL + (pj4 << 2));
        vr[rep] = *(const float4*)(vp + (rep * 16 + pd) * NCOL + (pj4 << 2));
    }
    __syncthreads();

    for (int kt = 0; kt < 16; kt++) {
#pragma unroll
        for (int rep = 0; rep < 4; rep++) {
            int d = rep * 16 + pd;
            *(float4*)&Ks[d][pj4 << 2] = kr[rep];
            float4 vv = vr[rep];
            Vt[(pj4 << 2) + 0][d] = vv.x;
            Vt[(pj4 << 2) + 1][d] = vv.y;
            Vt[(pj4 << 2) + 2][d] = vv.z;
            Vt[(pj4 << 2) + 3][d] = vv.w;
        }
        __syncthreads();

        if (kt < 15) {
            int j0n = (kt + 1) << 6;
#pragma unroll
            for (int rep = 0; rep < 4; rep++) {
                kr[rep] = *(const float4*)(kp + (rep * 16 + pd) * NCOL + j0n + (pj4 << 2));
                vr[rep] = *(const float4*)(vp + (rep * 16 + pd) * NCOL + j0n + (pj4 << 2));
            }
        }

        float s[4][4];
#pragma unroll
        for (int a = 0; a < 4; a++)
#pragma unroll
            for (int c = 0; c < 4; c++) s[a][c] = 0.f;
#pragma unroll 16
        for (int d = 0; d < 64; d++) {
            float4 qa = *(const float4*)&Qs[d][ty << 2];
            float4 kb = *(const float4*)&Ks[d][tx << 2];
            s[0][0] = fmaf(qa.x, kb.x, s[0][0]); s[0][1] = fmaf(qa.x, kb.y, s[0][1]);
            s[0][2] = fmaf(qa.x, kb.z, s[0][2]); s[0][3] = fmaf(qa.x, kb.w, s[0][3]);
            s[1][0] = fmaf(qa.y, kb.x, s[1][0]); s[1][1] = fmaf(qa.y, kb.y, s[1][1]);
            s[1][2] = fmaf(qa.y, kb.z, s[1][2]); s[1][3] = fmaf(qa.y, kb.w, s[1][3]);
            s[2][0] = fmaf(qa.z, kb.x, s[2][0]); s[2][1] = fmaf(qa.z, kb.y, s[2][1]);
            s[2][2] = fmaf(qa.z, kb.z, s[2][2]); s[2][3] = fmaf(qa.z, kb.w, s[2][3]);
            s[3][0] = fmaf(qa.w, kb.x, s[3][0]); s[3][1] = fmaf(qa.w, kb.y, s[3][1]);
            s[3][2] = fmaf(qa.w, kb.z, s[3][2]); s[3][3] = fmaf(qa.w, kb.w, s[3][3]);
        }
        __syncthreads();

#pragma unroll
        for (int ii = 0; ii < 4; ii++) {
            float4 p;
            p.x = s[ii][0] * 0.125f; p.y = s[ii][1] * 0.125f;
            p.z = s[ii][2] * 0.125f; p.w = s[ii][3] * 0.125f;
            *(float4*)&Ss[((ty << 2) + ii) * 64 + (tx << 2)] = p;
        }
        __syncthreads();

        {
            int r = tid >> 2, part = tid & 3;
            float* row = &Ss[r * 64 + part * 16];
            float mx = -1e30f;
#pragma unroll
            for (int t = 0; t < 16; t++) mx = fmaxf(mx, row[t]);
            mx = fmaxf(mx, __shfl_xor_sync(0xffffffffu, mx, 1));
            mx = fmaxf(mx, __shfl_xor_sync(0xffffffffu, mx, 2));
            float m_old = m_s[r];
            float m_new = fmaxf(m_old, mx);
            float sum = 0.f;
#pragma unroll
            for (int t = 0; t < 16; t++) {
                float p = __expf(row[t] - m_new);
                row[t] = p;
                sum += p;
            }
            sum += __shfl_xor_sync(0xffffffffu, sum, 1);
            sum += __shfl_xor_sync(0xffffffffu, sum, 2);
            if (part == 0) {
                float al = __expf(m_old - m_new);
                m_s[r] = m_new;
                l_s[r] = l_s[r] * al + sum;
                alpha_s[r] = al;
            }
        }
        __syncthreads();

#pragma unroll
        for (int ii = 0; ii < 4; ii++) {
            float al = alpha_s[(ty << 2) + ii];
            acc[ii][0] *= al; acc[ii][1] *= al; acc[ii][2] *= al; acc[ii][3] *= al;
        }
#pragma unroll 8
        for (int j = 0; j < 64; j++) {
            float4 v4 = *(const float4*)&Vt[j][tx << 2];
#pragma unroll
            for (int ii = 0; ii < 4; ii++) {
                float p = Ss[((ty << 2) + ii) * 64 + j];
                acc[ii][0] = fmaf(p, v4.x, acc[ii][0]);
                acc[ii][1] = fmaf(p, v4.y, acc[ii][1]);
                acc[ii][2] = fmaf(p, v4.z, acc[ii][2]);
                acc[ii][3] = fmaf(p, v4.w, acc[ii][3]);
            }
        }
        __syncthreads();
    }

    // epilogue: normalize, write bf16 pixel-major: g_attn[n][head*64 + d]
#pragma unroll
    for (int ii = 0; ii < 4; ii++) {
        float inv = 1.f / l_s[(ty << 2) + ii];
        __nv_bfloat162 h0 = __floats2bfloat162_rn(acc[ii][0] * inv, acc[ii][1] * inv);
        __nv_bfloat162 h1 = __floats2bfloat162_rn(acc[ii][2] * inv, acc[ii][3] * inv);
        size_t off = (size_t)(b * 1024 + q0 + (ty << 2) + ii) * 512 + head * 64 + (tx << 2);
        *(uint2*)(g_attn + off) = make_uint2(*(unsigned*)&h0, *(unsigned*)&h1);
    }
}

#define ATTN_SMEM_BYTES 50944

// ---------------------------------------------------------------------------
extern "C" void kernel_launch(void* const* d_in, const int* in_sizes, int n_in,
                              void* d_out, int out_size)
{
    const float* x    = (const float*)d_in[0];
    const float* gnw  = (const float*)d_in[1];
    const float* gnb  = (const float*)d_in[2];
    const float* qkvw = (const float*)d_in[3];
    const float* qkvb = (const float*)d_in[4];
    const float* outw = (const float*)d_in[5];
    const float* outb = (const float*)d_in[6];
    float* out = (float*)d_out;

    float* qkv;
    __nv_bfloat16 *xnt, *attn, *wqkv, *wout;
    cudaGetSymbolAddress((void**)&qkv,  g_qkv);
    cudaGetSymbolAddress((void**)&xnt,  g_xnt);
    cudaGetSymbolAddress((void**)&attn, g_attn);
    cudaGetSymbolAddress((void**)&wqkv, g_wqkv);
    cudaGetSymbolAddress((void**)&wout, g_wout);

    cudaFuncSetAttribute(attn_kernel,
                         cudaFuncAttributeMaxDynamicSharedMemorySize,
                         ATTN_SMEM_BYTES);

    // 0. weights -> bf16
    cvt_kernel<<<1024, 256>>>(qkvw, outw);
    // 1. GroupNorm -> bf16 pixel-major activations
    gn_kernel<<<256, 256>>>(x, gnw, gnb);
    // 2. QKV projection (tensor cores): [1536,512] @ [512,8192] -> fp32 g_qkv
    hgemm_kernel<0><<<dim3(64, 12), 256>>>(wqkv, xnt, qkvb, nullptr, qkv);
    // 3. Flash attention (fp32) -> bf16 pixel-major g_attn
    attn_kernel<<<dim3(16, 64), 256, ATTN_SMEM_BYTES>>>();
    // 4. Out projection + bias + residual (tensor cores) -> d_out
    hgemm_kernel<1><<<dim3(64, 4), 256>>>(wout, attn, outb, x, out);
}